// round 2
// baseline (speedup 1.0000x reference)
#include <cuda_runtime.h>

// ---------------- problem constants ----------------
#define NB 4096
#define IMG 128
#define WIN 112
#define WSTR 113

// ---------------- scratch ----------------
__device__ float  g_phi[NB * 784];
__device__ float  g_h1w[NB * 128];
__device__ float  g_h1l[NB * 128];
__device__ float  g_h2w[NB * 256];
__device__ float  g_h2l[NB * 256];
__device__ float  g_bn[1536];          // sc/sh: [0]=1w sc,[128]=1w sh,[256]=1l sc,[384]=1l sh,[512]=2w sc,[768]=2w sh,[1024]=2l sc,[1280]=2l sh
__device__ float  g_p1s[64 * 128];     // gemm1 per-yblock column sums
__device__ float  g_p1q[64 * 128];
__device__ float  g_p2s[2][64 * 256];  // gemm2 partials (0=what,1=where)
__device__ float  g_p2q[2][64 * 256];
__device__ double g_locstat[5];        // S0,S1,Q00,Q11,Q01

// ---------------- packed f32x2 helpers ----------------
__device__ __forceinline__ void ffma2(unsigned long long& d, unsigned long long a, unsigned long long b) {
    asm("fma.rn.f32x2 %0, %1, %2, %0;" : "+l"(d) : "l"(a), "l"(b));
}
__device__ __forceinline__ unsigned long long pk2(float lo, float hi) {
    unsigned long long r; asm("mov.b64 %0, {%1, %2};" : "=l"(r) : "f"(lo), "f"(hi)); return r;
}
__device__ __forceinline__ float2 upk2(unsigned long long v) {
    float2 f; asm("mov.b64 {%0, %1}, %2;" : "=f"(f.x), "=f"(f.y) : "l"(v)); return f;
}

// ---------------- loc moments (for analytic where-BN1) ----------------
__global__ void locstats_kernel(const float* __restrict__ loc) {
    __shared__ float red[5][32];
    int tid = threadIdx.x;                // 1024
    float s0 = 0, s1 = 0, q00 = 0, q11 = 0, q01 = 0;
    for (int r = tid; r < NB; r += 1024) {
        float a = loc[2 * r], b = loc[2 * r + 1];
        s0 += a; s1 += b;
        q00 = fmaf(a, a, q00); q11 = fmaf(b, b, q11); q01 = fmaf(a, b, q01);
    }
#pragma unroll
    for (int o = 16; o > 0; o >>= 1) {
        s0  += __shfl_down_sync(0xffffffffu, s0, o);
        s1  += __shfl_down_sync(0xffffffffu, s1, o);
        q00 += __shfl_down_sync(0xffffffffu, q00, o);
        q11 += __shfl_down_sync(0xffffffffu, q11, o);
        q01 += __shfl_down_sync(0xffffffffu, q01, o);
    }
    int lane = tid & 31, w = tid >> 5;
    if (lane == 0) { red[0][w] = s0; red[1][w] = s1; red[2][w] = q00; red[3][w] = q11; red[4][w] = q01; }
    __syncthreads();
    if (tid < 5) {
        double acc = 0.0;
        for (int i = 0; i < 32; i++) acc += (double)red[tid][i];
        g_locstat[tid] = acc;
    }
}

// ---------------- foveate + fused where layer1 ----------------
__global__ void foveate_kernel(const float* __restrict__ x, const float* __restrict__ loc,
                               const float* __restrict__ lW1, const float* __restrict__ lb1) {
    extern __shared__ float sh[];  // WIN * WSTR
    const int b = blockIdx.x;
    const int tid = threadIdx.x;
    const float lx = loc[2 * b + 0];
    const float ly = loc[2 * b + 1];
    const int cx = (int)(0.5f * ((lx + 1.0f) * 128.0f));
    const int cy = (int)(0.5f * ((ly + 1.0f) * 128.0f));
    const int y0 = cy - 56;
    const int x0 = cx - 56;
    const float* img = x + (size_t)b * (IMG * IMG);

    // zero window (covers OOB regions)
    for (int i = tid; i < WIN * WSTR; i += 256) sh[i] = 0.0f;
    __syncthreads();

    // aligned full-row loads: only in-bounds rows, all 128 cols, keep those in window
    int rlo = max(0, -y0), rhi = min(WIN, IMG - y0);
    int nrows = rhi - rlo;
    for (int t = tid; t < nrows * IMG; t += 256) {
        int r = rlo + (t >> 7);
        int c = t & 127;
        int scn = c - x0;
        if ((unsigned)scn < (unsigned)WIN) sh[r * WSTR + scn] = img[(y0 + r) * IMG + c];
    }
    __syncthreads();

    float* out = g_phi + (size_t)b * 784;
    for (int idx = tid; idx < 784; idx += 256) {
        int l = idx / 196;
        int rem = idx - l * 196;
        int i = rem / 14;
        int j = rem - i * 14;
        int k = 1 << l;
        int off = 56 - 7 * k;
        int base = (off + i * k) * WSTR + (off + j * k);
        float s = 0.0f;
        for (int ky = 0; ky < k; ky++) {
            int rb = base + ky * WSTR;
            for (int kx = 0; kx < k; kx++) s += sh[rb + kx];
        }
        out[idx] = s * (1.0f / (float)(k * k));
    }

    // fused where layer1: h1l[b][j] = lx*W[0,j] + ly*W[1,j] + b1[j]
    if (tid < 128)
        g_h1l[b * 128 + tid] = fmaf(lx, lW1[tid], fmaf(ly, lW1[128 + tid], lb1[tid]));
}

// ---------------- gemm1: h1w = phi @ W1 + b1, fused column-stat partials ----------------
// M=4096 N=128 K=784; BM=BN=64, BK=16, 256 thr, TM=TN=4; grid (2, 64)
__global__ void __launch_bounds__(256, 4)
gemm1_kernel(const float* __restrict__ A, const float* __restrict__ W,
             const float* __restrict__ bias, float* __restrict__ C) {
    constexpr int BM = 64, BN = 64, BK = 16, TM = 4;
    __shared__ float As[BK * (BM + 1)];
    __shared__ float Bs[BK * BN];
    __shared__ float red[16 * 64];

    const int K = 784, N = 128;
    const int tid = threadIdx.x;
    const int m0 = blockIdx.y * BM;
    const int n0 = blockIdx.x * BN;
    const int tx = tid & 15;
    const int ty = tid >> 4;

    unsigned long long acc2[TM][2];
#pragma unroll
    for (int i = 0; i < TM; i++) { acc2[i][0] = 0ull; acc2[i][1] = 0ull; }

    for (int k0 = 0; k0 < K; k0 += BK) {
#pragma unroll
        for (int it = 0; it < 4; ++it) {
            int ka = tid & 15;
            int ma = (tid >> 4) + it * 16;
            As[ka * (BM + 1) + ma] = A[(size_t)(m0 + ma) * K + (k0 + ka)];
        }
#pragma unroll
        for (int it = 0; it < 4; ++it) {
            int nb = tid & 63;
            int kb = (tid >> 6) + it * 4;
            Bs[kb * BN + nb] = W[(size_t)(k0 + kb) * N + (n0 + nb)];
        }
        __syncthreads();
#pragma unroll
        for (int kk = 0; kk < BK; kk++) {
            unsigned long long b01 = *reinterpret_cast<const unsigned long long*>(&Bs[kk * BN + tx * 4]);
            unsigned long long b23 = *reinterpret_cast<const unsigned long long*>(&Bs[kk * BN + tx * 4 + 2]);
#pragma unroll
            for (int i = 0; i < TM; i++) {
                float a = As[kk * (BM + 1) + ty * TM + i];
                unsigned long long ad = pk2(a, a);
                ffma2(acc2[i][0], ad, b01);
                ffma2(acc2[i][1], ad, b23);
            }
        }
        __syncthreads();
    }

    // bias + store + per-thread column partials
    float cs[4] = {0, 0, 0, 0}, cq[4] = {0, 0, 0, 0};
    float bb[4];
#pragma unroll
    for (int j = 0; j < 4; j++) bb[j] = bias[n0 + tx * 4 + j];
#pragma unroll
    for (int i = 0; i < TM; i++) {
        int m = m0 + ty * TM + i;
        float2 v0 = upk2(acc2[i][0]);
        float2 v1 = upk2(acc2[i][1]);
        float c0 = v0.x + bb[0], c1 = v0.y + bb[1], c2 = v1.x + bb[2], c3 = v1.y + bb[3];
        float* cp = &C[(size_t)m * N + n0 + tx * 4];
        cp[0] = c0; cp[1] = c1; cp[2] = c2; cp[3] = c3;
        cs[0] += c0; cs[1] += c1; cs[2] += c2; cs[3] += c3;
        cq[0] = fmaf(c0, c0, cq[0]); cq[1] = fmaf(c1, c1, cq[1]);
        cq[2] = fmaf(c2, c2, cq[2]); cq[3] = fmaf(c3, c3, cq[3]);
    }
#pragma unroll
    for (int j = 0; j < 4; j++) red[ty * 64 + tx * 4 + j] = cs[j];
    __syncthreads();
    if (tid < 64) {
        float s = 0;
        for (int t = 0; t < 16; t++) s += red[t * 64 + tid];
        g_p1s[blockIdx.y * N + n0 + tid] = s;
    }
    __syncthreads();
#pragma unroll
    for (int j = 0; j < 4; j++) red[ty * 64 + tx * 4 + j] = cq[j];
    __syncthreads();
    if (tid < 64) {
        float s = 0;
        for (int t = 0; t < 16; t++) s += red[t * 64 + tid];
        g_p1q[blockIdx.y * N + n0 + tid] = s;
    }
}

// ---------------- finalize BN1 (what via partials, where analytic) ----------------
__global__ void finalize1_kernel(const float* __restrict__ wg1, const float* __restrict__ wbe1,
                                 const float* __restrict__ lW1, const float* __restrict__ lb1,
                                 const float* __restrict__ lg1, const float* __restrict__ lbe1) {
    int tid = threadIdx.x;  // 256
    if (tid < 128) {
        double s = 0, q = 0;
        for (int y = 0; y < 64; y++) { s += (double)g_p1s[y * 128 + tid]; q += (double)g_p1q[y * 128 + tid]; }
        double m = s * (1.0 / NB);
        double var = q * (1.0 / NB) - m * m;
        float scale = wg1[tid] * rsqrtf((float)var + 1e-5f);
        g_bn[tid] = scale;
        g_bn[128 + tid] = wbe1[tid] - (float)m * scale;
    } else {
        int j = tid - 128;
        double m0 = g_locstat[0] * (1.0 / NB), m1 = g_locstat[1] * (1.0 / NB);
        double v00 = g_locstat[2] * (1.0 / NB) - m0 * m0;
        double v11 = g_locstat[3] * (1.0 / NB) - m1 * m1;
        double v01 = g_locstat[4] * (1.0 / NB) - m0 * m1;
        double W0 = (double)lW1[j], W1 = (double)lW1[128 + j];
        double mean = m0 * W0 + m1 * W1 + (double)lb1[j];
        double var = W0 * W0 * v00 + W1 * W1 * v11 + 2.0 * W0 * W1 * v01;
        float scale = lg1[j] * rsqrtf((float)var + 1e-5f);
        g_bn[256 + j] = scale;
        g_bn[384 + j] = lbe1[j] - (float)mean * scale;
    }
}

// ---------------- gemm2 (both paths via z): h2 = relu(BN1(h1)) @ W2 + b2 ----------------
// M=4096 N=256 K=128; BM=BN=64, BK=16; grid (4, 64, 2)
__global__ void __launch_bounds__(256, 4)
gemm2_kernel(const float* __restrict__ W2w, const float* __restrict__ b2w,
             const float* __restrict__ W2l, const float* __restrict__ b2l) {
    constexpr int BM = 64, BN = 64, BK = 16, TM = 4;
    __shared__ float As[BK * (BM + 1)];
    __shared__ float Bs[BK * BN];
    __shared__ float red[16 * 64];

    const int K = 128, N = 256;
    const int z = blockIdx.z;
    const float* A    = z ? g_h1l : g_h1w;
    const float* W    = z ? W2l : W2w;
    const float* bias = z ? b2l : b2w;
    float* C          = z ? g_h2l : g_h2w;
    const float* bnsc = g_bn + (z ? 256 : 0);
    const float* bnsh = g_bn + (z ? 384 : 128);
    float* psum = z ? g_p2s[1] : g_p2s[0];
    float* psq  = z ? g_p2q[1] : g_p2q[0];

    const int tid = threadIdx.x;
    const int m0 = blockIdx.y * BM;
    const int n0 = blockIdx.x * BN;
    const int tx = tid & 15;
    const int ty = tid >> 4;

    unsigned long long acc2[TM][2];
#pragma unroll
    for (int i = 0; i < TM; i++) { acc2[i][0] = 0ull; acc2[i][1] = 0ull; }

    for (int k0 = 0; k0 < K; k0 += BK) {
#pragma unroll
        for (int it = 0; it < 4; ++it) {
            int ka = tid & 15;
            int ma = (tid >> 4) + it * 16;
            float v = A[(size_t)(m0 + ma) * K + (k0 + ka)];
            v = fmaxf(fmaf(v, bnsc[k0 + ka], bnsh[k0 + ka]), 0.0f);
            As[ka * (BM + 1) + ma] = v;
        }
#pragma unroll
        for (int it = 0; it < 4; ++it) {
            int nb = tid & 63;
            int kb = (tid >> 6) + it * 4;
            Bs[kb * BN + nb] = W[(size_t)(k0 + kb) * N + (n0 + nb)];
        }
        __syncthreads();
#pragma unroll
        for (int kk = 0; kk < BK; kk++) {
            unsigned long long b01 = *reinterpret_cast<const unsigned long long*>(&Bs[kk * BN + tx * 4]);
            unsigned long long b23 = *reinterpret_cast<const unsigned long long*>(&Bs[kk * BN + tx * 4 + 2]);
#pragma unroll
            for (int i = 0; i < TM; i++) {
                float a = As[kk * (BM + 1) + ty * TM + i];
                unsigned long long ad = pk2(a, a);
                ffma2(acc2[i][0], ad, b01);
                ffma2(acc2[i][1], ad, b23);
            }
        }
        __syncthreads();
    }

    float cs[4] = {0, 0, 0, 0}, cq[4] = {0, 0, 0, 0};
    float bb[4];
#pragma unroll
    for (int j = 0; j < 4; j++) bb[j] = bias[n0 + tx * 4 + j];
#pragma unroll
    for (int i = 0; i < TM; i++) {
        int m = m0 + ty * TM + i;
        float2 v0 = upk2(acc2[i][0]);
        float2 v1 = upk2(acc2[i][1]);
        float c0 = v0.x + bb[0], c1 = v0.y + bb[1], c2 = v1.x + bb[2], c3 = v1.y + bb[3];
        float* cp = &C[(size_t)m * N + n0 + tx * 4];
        cp[0] = c0; cp[1] = c1; cp[2] = c2; cp[3] = c3;
        cs[0] += c0; cs[1] += c1; cs[2] += c2; cs[3] += c3;
        cq[0] = fmaf(c0, c0, cq[0]); cq[1] = fmaf(c1, c1, cq[1]);
        cq[2] = fmaf(c2, c2, cq[2]); cq[3] = fmaf(c3, c3, cq[3]);
    }
#pragma unroll
    for (int j = 0; j < 4; j++) red[ty * 64 + tx * 4 + j] = cs[j];
    __syncthreads();
    if (tid < 64) {
        float s = 0;
        for (int t = 0; t < 16; t++) s += red[t * 64 + tid];
        psum[blockIdx.y * N + n0 + tid] = s;
    }
    __syncthreads();
#pragma unroll
    for (int j = 0; j < 4; j++) red[ty * 64 + tx * 4 + j] = cq[j];
    __syncthreads();
    if (tid < 64) {
        float s = 0;
        for (int t = 0; t < 16; t++) s += red[t * 64 + tid];
        psq[blockIdx.y * N + n0 + tid] = s;
    }
}

// ---------------- finalize BN2 (both paths) ----------------
__global__ void finalize2_kernel(const float* __restrict__ wg2, const float* __restrict__ wbe2,
                                 const float* __restrict__ lg2, const float* __restrict__ lbe2) {
    int tid = threadIdx.x;  // 512
    int p = tid >> 8;
    int j = tid & 255;
    const float* ps = g_p2s[p];
    const float* pq = g_p2q[p];
    double s = 0, q = 0;
    for (int y = 0; y < 64; y++) { s += (double)ps[y * 256 + j]; q += (double)pq[y * 256 + j]; }
    double m = s * (1.0 / NB);
    double var = q * (1.0 / NB) - m * m;
    const float* g  = p ? lg2 : wg2;
    const float* be = p ? lbe2 : wbe2;
    float scale = g[j] * rsqrtf((float)var + 1e-5f);
    int off = p ? 1024 : 512;
    g_bn[off + j] = scale;
    g_bn[off + 256 + j] = be[j] - (float)m * scale;
}

// ---------------- final: out = relu(BN2w(h2w) + BN2l(h2l)) ----------------
__global__ void final_kernel(float* __restrict__ out) {
    int idx = blockIdx.x * blockDim.x + threadIdx.x;  // NB*256
    int j = idx & 255;
    float vw = fmaf(g_h2w[idx], g_bn[512 + j], g_bn[768 + j]);
    float vl = fmaf(g_h2l[idx], g_bn[1024 + j], g_bn[1280 + j]);
    out[idx] = fmaxf(vw + vl, 0.0f);
}

// ---------------- launch ----------------
extern "C" void kernel_launch(void* const* d_in, const int* in_sizes, int n_in,
                              void* d_out, int out_size) {
    const float* x    = (const float*)d_in[0];
    const float* loc  = (const float*)d_in[1];
    const float* wW1  = (const float*)d_in[2];
    const float* wb1  = (const float*)d_in[3];
    const float* wg1  = (const float*)d_in[4];
    const float* wbe1 = (const float*)d_in[5];
    const float* wW2  = (const float*)d_in[6];
    const float* wb2  = (const float*)d_in[7];
    const float* wg2  = (const float*)d_in[8];
    const float* wbe2 = (const float*)d_in[9];
    const float* lW1  = (const float*)d_in[10];
    const float* lb1  = (const float*)d_in[11];
    const float* lg1  = (const float*)d_in[12];
    const float* lbe1 = (const float*)d_in[13];
    const float* lW2  = (const float*)d_in[14];
    const float* lb2  = (const float*)d_in[15];
    const float* lg2  = (const float*)d_in[16];
    const float* lbe2 = (const float*)d_in[17];
    float* out = (float*)d_out;

    float *phi, *h1w;
    cudaGetSymbolAddress((void**)&phi, g_phi);
    cudaGetSymbolAddress((void**)&h1w, g_h1w);

    const int smem_fov = WIN * WSTR * sizeof(float);
    cudaFuncSetAttribute(foveate_kernel, cudaFuncAttributeMaxDynamicSharedMemorySize, smem_fov);

    locstats_kernel<<<1, 1024>>>(loc);
    foveate_kernel<<<NB, 256, smem_fov>>>(x, loc, lW1, lb1);
    gemm1_kernel<<<dim3(2, 64), 256>>>(phi, wW1, wb1, h1w);
    finalize1_kernel<<<1, 256>>>(wg1, wbe1, lW1, lb1, lg1, lbe1);
    gemm2_kernel<<<dim3(4, 64, 2), 256>>>(wW2, wb2, lW2, lb2);
    finalize2_kernel<<<1, 512>>>(wg2, wbe2, lg2, lbe2);
    final_kernel<<<(NB * 256) / 256, 256>>>(out);
}

// round 3
// speedup vs baseline: 1.3867x; 1.3867x over previous
#include <cuda_runtime.h>

// ---------------- problem constants ----------------
#define NB 4096
#define IMG 128
#define WIN 112
#define WSTR 113

// stat buffer layout (floats)
#define ST_LOC 0     // 5: Sx, Sy, Qxx, Qyy, Qxy
#define ST_S1  8     // 128
#define ST_Q1  136   // 128
#define ST_S2W 264   // 256
#define ST_Q2W 520   // 256
#define ST_S2L 776   // 256
#define ST_Q2L 1032  // 256
#define ST_TOTAL 1288

// ---------------- scratch ----------------
__device__ float g_phi[NB * 784];
__device__ float g_h1p[4 * NB * 128];   // gemm1 split-K partials
__device__ float g_h1w[NB * 128];
__device__ float g_h1l[NB * 128];
__device__ float g_h2w[NB * 256];
__device__ float g_h2l[NB * 256];
__device__ float g_stat[ST_TOTAL];

// ---------------- packed f32x2 helpers ----------------
__device__ __forceinline__ void ffma2(unsigned long long& d, unsigned long long a, unsigned long long b) {
    asm("fma.rn.f32x2 %0, %1, %2, %0;" : "+l"(d) : "l"(a), "l"(b));
}
__device__ __forceinline__ unsigned long long pk2(float lo, float hi) {
    unsigned long long r; asm("mov.b64 %0, {%1, %2};" : "=l"(r) : "f"(lo), "f"(hi)); return r;
}
__device__ __forceinline__ float2 upk2(unsigned long long v) {
    float2 f; asm("mov.b64 {%0, %1}, %2;" : "=f"(f.x), "=f"(f.y) : "l"(v)); return f;
}

// ---------------- foveate + fused where layer1 + loc moment atomics ----------------
__global__ void foveate_kernel(const float* __restrict__ x, const float* __restrict__ loc,
                               const float* __restrict__ lW1, const float* __restrict__ lb1) {
    extern __shared__ float sh[];  // WIN * WSTR
    const int b = blockIdx.x;
    const int tid = threadIdx.x;
    const float lx = loc[2 * b + 0];
    const float ly = loc[2 * b + 1];
    const int cx = (int)(0.5f * ((lx + 1.0f) * 128.0f));
    const int cy = (int)(0.5f * ((ly + 1.0f) * 128.0f));
    const int y0 = cy - 56;
    const int x0 = cx - 56;
    const float* img = x + (size_t)b * (IMG * IMG);

    if (tid == 0) {
        atomicAdd(&g_stat[ST_LOC + 0], lx);
        atomicAdd(&g_stat[ST_LOC + 1], ly);
        atomicAdd(&g_stat[ST_LOC + 2], lx * lx);
        atomicAdd(&g_stat[ST_LOC + 3], ly * ly);
        atomicAdd(&g_stat[ST_LOC + 4], lx * ly);
    }

    for (int i = tid; i < WIN * WSTR; i += 256) sh[i] = 0.0f;
    __syncthreads();

    int rlo = max(0, -y0), rhi = min(WIN, IMG - y0);
    int nrows = rhi - rlo;
    for (int t = tid; t < nrows * IMG; t += 256) {
        int r = rlo + (t >> 7);
        int c = t & 127;
        int scn = c - x0;
        if ((unsigned)scn < (unsigned)WIN) sh[r * WSTR + scn] = img[(y0 + r) * IMG + c];
    }
    __syncthreads();

    float* out = g_phi + (size_t)b * 784;
    for (int idx = tid; idx < 784; idx += 256) {
        int l = idx / 196;
        int rem = idx - l * 196;
        int i = rem / 14;
        int j = rem - i * 14;
        int k = 1 << l;
        int off = 56 - 7 * k;
        int base = (off + i * k) * WSTR + (off + j * k);
        float s = 0.0f;
        for (int ky = 0; ky < k; ky++) {
            int rb = base + ky * WSTR;
            for (int kx = 0; kx < k; kx++) s += sh[rb + kx];
        }
        out[idx] = s * (1.0f / (float)(k * k));
    }

    if (tid < 128)
        g_h1l[b * 128 + tid] = fmaf(lx, lW1[tid], fmaf(ly, lW1[128 + tid], lb1[tid]));
}

// ---------------- gemm1: split-K partials of phi @ W1 ----------------
// M=4096, N=128, K=784. BM=128, BN=128(=N), BK=8, 256 thr, TM=TN=8.
// grid: (32 m-blocks, 4 k-splits). Partials -> g_h1p[z].
__global__ void __launch_bounds__(256)
gemm1_kernel(const float* __restrict__ A, const float* __restrict__ W) {
    __shared__ float As[2][8 * 132];
    __shared__ float Bs[2][8 * 128];
    const int tid = threadIdx.x;
    const int m0 = blockIdx.x * 128;
    const int z = blockIdx.y;
    const int kb = z * 200;
    const int ntiles = (z < 3) ? 25 : 23;  // 200/8 or 184/8
    const int K = 784, N = 128;
    const int tx = tid & 15, ty = tid >> 4;

    const int ka = tid & 7, mBase = tid >> 3;   // A: 4 iters, rows mBase + it*32
    const int bc4 = tid & 31, bk = tid >> 5;    // B: one float4, rows 0..7

    float ar[4]; float4 br;
    // tile 0
    {
        const float* Ap = A + (size_t)(m0 + mBase) * K + kb + ka;
#pragma unroll
        for (int it = 0; it < 4; it++) ar[it] = Ap[(size_t)it * 32 * K];
        br = *(const float4*)&W[(size_t)(kb + bk) * N + bc4 * 4];
#pragma unroll
        for (int it = 0; it < 4; it++) As[0][ka * 132 + mBase + it * 32] = ar[it];
        *(float4*)&Bs[0][bk * 128 + bc4 * 4] = br;
    }
    __syncthreads();

    unsigned long long acc[8][4];
#pragma unroll
    for (int i = 0; i < 8; i++)
#pragma unroll
        for (int j = 0; j < 4; j++) acc[i][j] = 0ull;

    int buf = 0;
    for (int t = 0; t < ntiles; t++) {
        if (t + 1 < ntiles) {
            int k0 = kb + (t + 1) * 8;
            const float* Ap = A + (size_t)(m0 + mBase) * K + k0 + ka;
#pragma unroll
            for (int it = 0; it < 4; it++) ar[it] = Ap[(size_t)it * 32 * K];
            br = *(const float4*)&W[(size_t)(k0 + bk) * N + bc4 * 4];
        }
#pragma unroll
        for (int kk = 0; kk < 8; kk++) {
            float4 a0 = *(float4*)&As[buf][kk * 132 + ty * 8];
            float4 a1 = *(float4*)&As[buf][kk * 132 + ty * 8 + 4];
            float4 b0 = *(float4*)&Bs[buf][kk * 128 + tx * 8];
            float4 b1 = *(float4*)&Bs[buf][kk * 128 + tx * 8 + 4];
            unsigned long long bp0 = pk2(b0.x, b0.y), bp1 = pk2(b0.z, b0.w);
            unsigned long long bp2 = pk2(b1.x, b1.y), bp3 = pk2(b1.z, b1.w);
            float av[8] = {a0.x, a0.y, a0.z, a0.w, a1.x, a1.y, a1.z, a1.w};
#pragma unroll
            for (int i = 0; i < 8; i++) {
                unsigned long long ad = pk2(av[i], av[i]);
                ffma2(acc[i][0], ad, bp0);
                ffma2(acc[i][1], ad, bp1);
                ffma2(acc[i][2], ad, bp2);
                ffma2(acc[i][3], ad, bp3);
            }
        }
        if (t + 1 < ntiles) {
            buf ^= 1;
#pragma unroll
            for (int it = 0; it < 4; it++) As[buf][ka * 132 + mBase + it * 32] = ar[it];
            *(float4*)&Bs[buf][bk * 128 + bc4 * 4] = br;
            __syncthreads();
        }
    }

    float* Cp = g_h1p + ((size_t)z * NB + m0) * 128;
#pragma unroll
    for (int i = 0; i < 8; i++) {
        float2 v0 = upk2(acc[i][0]), v1 = upk2(acc[i][1]);
        float2 v2 = upk2(acc[i][2]), v3 = upk2(acc[i][3]);
        float4 o0 = {v0.x, v0.y, v1.x, v1.y};
        float4 o1 = {v2.x, v2.y, v3.x, v3.y};
        float* cp = Cp + (size_t)(ty * 8 + i) * 128 + tx * 8;
        *(float4*)cp = o0;
        *(float4*)(cp + 4) = o1;
    }
}

// ---------------- reduce split-K partials + bias -> h1w, emit BN1 stats ----------------
// grid 128 blocks x 256 thr; each block: 32 rows.
__global__ void reduce1_kernel(const float* __restrict__ bias) {
    __shared__ float rs[256], rq[256];
    const int tid = threadIdx.x;
    const int col = tid & 127;
    const int grp = tid >> 7;
    const int r0 = blockIdx.x * 32 + grp * 16;
    const float b = bias[col];
    const size_t P = (size_t)NB * 128;
    float s = 0.0f, q = 0.0f;
    for (int r = 0; r < 16; r++) {
        size_t off = (size_t)(r0 + r) * 128 + col;
        float v = g_h1p[off] + g_h1p[P + off] + g_h1p[2 * P + off] + g_h1p[3 * P + off] + b;
        g_h1w[off] = v;
        s += v;
        q = fmaf(v, v, q);
    }
    rs[tid] = s; rq[tid] = q;
    __syncthreads();
    if (tid < 128) {
        atomicAdd(&g_stat[ST_S1 + tid], rs[tid] + rs[tid + 128]);
        atomicAdd(&g_stat[ST_Q1 + tid], rq[tid] + rq[tid + 128]);
    }
}

// ---------------- gemm2: h2 = relu(BN1(h1)) @ W2 + b2, both paths, fused stats ----------------
// M=4096, N=256, K=128. BM=BN=128, BK=8, 256 thr, TM=TN=8.
// grid: (2 n-blocks, 32 m-blocks, 2 paths)
__global__ void __launch_bounds__(256)
gemm2_kernel(const float* __restrict__ wW2, const float* __restrict__ wb2,
             const float* __restrict__ lW2, const float* __restrict__ lb2,
             const float* __restrict__ wg1, const float* __restrict__ wbe1,
             const float* __restrict__ lW1, const float* __restrict__ lb1,
             const float* __restrict__ lg1, const float* __restrict__ lbe1) {
    __shared__ float As[2][8 * 132];
    __shared__ float Bs[2][8 * 128];
    __shared__ float sSC[128], sSH[128];

    const int tid = threadIdx.x;
    const int n0 = blockIdx.x * 128;
    const int m0 = blockIdx.y * 128;
    const int path = blockIdx.z;
    const int K = 128, N = 256;
    const int tx = tid & 15, ty = tid >> 4;

    const float* A    = path ? g_h1l : g_h1w;
    const float* W    = path ? lW2 : wW2;
    const float* bias = path ? lb2 : wb2;
    float* C          = path ? g_h2l : g_h2w;
    float* statS = g_stat + (path ? ST_S2L : ST_S2W);
    float* statQ = g_stat + (path ? ST_Q2L : ST_Q2W);

    // prologue: BN1 scale/shift for this path
    if (tid < 128) {
        const float inv = 1.0f / (float)NB;
        float sc, shv;
        if (path == 0) {
            float m = g_stat[ST_S1 + tid] * inv;
            float var = g_stat[ST_Q1 + tid] * inv - m * m;
            sc = wg1[tid] * rsqrtf(var + 1e-5f);
            shv = wbe1[tid] - m * sc;
        } else {
            float m0l = g_stat[0] * inv, m1l = g_stat[1] * inv;
            float v00 = g_stat[2] * inv - m0l * m0l;
            float v11 = g_stat[3] * inv - m1l * m1l;
            float v01 = g_stat[4] * inv - m0l * m1l;
            float W0 = lW1[tid], W1 = lW1[128 + tid];
            float mean = fmaf(m0l, W0, fmaf(m1l, W1, lb1[tid]));
            float var = W0 * W0 * v00 + W1 * W1 * v11 + 2.0f * W0 * W1 * v01;
            sc = lg1[tid] * rsqrtf(var + 1e-5f);
            shv = lbe1[tid] - mean * sc;
        }
        sSC[tid] = sc; sSH[tid] = shv;
    }
    __syncthreads();

    const int ka = tid & 7, mBase = tid >> 3;
    const int bc4 = tid & 31, bk = tid >> 5;

    float ar[4]; float4 br;
    {
        const float* Ap = A + (size_t)(m0 + mBase) * K + ka;
#pragma unroll
        for (int it = 0; it < 4; it++) ar[it] = Ap[(size_t)it * 32 * K];
        br = *(const float4*)&W[(size_t)bk * N + n0 + bc4 * 4];
        float scv = sSC[ka], shv = sSH[ka];
#pragma unroll
        for (int it = 0; it < 4; it++)
            As[0][ka * 132 + mBase + it * 32] = fmaxf(fmaf(ar[it], scv, shv), 0.0f);
        *(float4*)&Bs[0][bk * 128 + bc4 * 4] = br;
    }
    __syncthreads();

    unsigned long long acc[8][4];
#pragma unroll
    for (int i = 0; i < 8; i++)
#pragma unroll
        for (int j = 0; j < 4; j++) acc[i][j] = 0ull;

    int buf = 0;
    const int ntiles = 16;
    for (int t = 0; t < ntiles; t++) {
        if (t + 1 < ntiles) {
            int k0 = (t + 1) * 8;
            const float* Ap = A + (size_t)(m0 + mBase) * K + k0 + ka;
#pragma unroll
            for (int it = 0; it < 4; it++) ar[it] = Ap[(size_t)it * 32 * K];
            br = *(const float4*)&W[(size_t)(k0 + bk) * N + n0 + bc4 * 4];
        }
#pragma unroll
        for (int kk = 0; kk < 8; kk++) {
            float4 a0 = *(float4*)&As[buf][kk * 132 + ty * 8];
            float4 a1 = *(float4*)&As[buf][kk * 132 + ty * 8 + 4];
            float4 b0 = *(float4*)&Bs[buf][kk * 128 + tx * 8];
            float4 b1 = *(float4*)&Bs[buf][kk * 128 + tx * 8 + 4];
            unsigned long long bp0 = pk2(b0.x, b0.y), bp1 = pk2(b0.z, b0.w);
            unsigned long long bp2 = pk2(b1.x, b1.y), bp3 = pk2(b1.z, b1.w);
            float av[8] = {a0.x, a0.y, a0.z, a0.w, a1.x, a1.y, a1.z, a1.w};
#pragma unroll
            for (int i = 0; i < 8; i++) {
                unsigned long long ad = pk2(av[i], av[i]);
                ffma2(acc[i][0], ad, bp0);
                ffma2(acc[i][1], ad, bp1);
                ffma2(acc[i][2], ad, bp2);
                ffma2(acc[i][3], ad, bp3);
            }
        }
        if (t + 1 < ntiles) {
            buf ^= 1;
            int k0 = (t + 1) * 8;
            float scv = sSC[k0 + ka], shv = sSH[k0 + ka];
#pragma unroll
            for (int it = 0; it < 4; it++)
                As[buf][ka * 132 + mBase + it * 32] = fmaxf(fmaf(ar[it], scv, shv), 0.0f);
            *(float4*)&Bs[buf][bk * 128 + bc4 * 4] = br;
            __syncthreads();
        }
    }

    // epilogue: bias, store, column stats
    float bb[8];
#pragma unroll
    for (int j = 0; j < 8; j++) bb[j] = bias[n0 + tx * 8 + j];
    float cv[8][8];
#pragma unroll
    for (int i = 0; i < 8; i++) {
        float2 v0 = upk2(acc[i][0]), v1 = upk2(acc[i][1]);
        float2 v2 = upk2(acc[i][2]), v3 = upk2(acc[i][3]);
        cv[i][0] = v0.x + bb[0]; cv[i][1] = v0.y + bb[1];
        cv[i][2] = v1.x + bb[2]; cv[i][3] = v1.y + bb[3];
        cv[i][4] = v2.x + bb[4]; cv[i][5] = v2.y + bb[5];
        cv[i][6] = v3.x + bb[6]; cv[i][7] = v3.y + bb[7];
        float* cp = C + (size_t)(m0 + ty * 8 + i) * N + n0 + tx * 8;
        float4 o0 = {cv[i][0], cv[i][1], cv[i][2], cv[i][3]};
        float4 o1 = {cv[i][4], cv[i][5], cv[i][6], cv[i][7]};
        *(float4*)cp = o0;
        *(float4*)(cp + 4) = o1;
    }
    float cs[8], cq[8];
#pragma unroll
    for (int j = 0; j < 8; j++) {
        float s = 0, q = 0;
#pragma unroll
        for (int i = 0; i < 8; i++) { s += cv[i][j]; q = fmaf(cv[i][j], cv[i][j], q); }
        cs[j] = s; cq[j] = q;
    }
    __syncthreads();
    float* red = &Bs[0][0];  // 2048 floats
#pragma unroll
    for (int j = 0; j < 8; j++) red[ty * 128 + tx * 8 + j] = cs[j];
    __syncthreads();
    if (tid < 128) {
        float s = 0;
#pragma unroll
        for (int t = 0; t < 16; t++) s += red[t * 128 + tid];
        atomicAdd(&statS[n0 + tid], s);
    }
    __syncthreads();
#pragma unroll
    for (int j = 0; j < 8; j++) red[ty * 128 + tx * 8 + j] = cq[j];
    __syncthreads();
    if (tid < 128) {
        float s = 0;
#pragma unroll
        for (int t = 0; t < 16; t++) s += red[t * 128 + tid];
        atomicAdd(&statQ[n0 + tid], s);
    }
}

// ---------------- final: per-block BN2 + relu(BNw + BNl) ----------------
__global__ void final_kernel(const float* __restrict__ wg2, const float* __restrict__ wbe2,
                             const float* __restrict__ lg2, const float* __restrict__ lbe2,
                             float* __restrict__ out) {
    __shared__ float scw[256], shw[256], scl[256], shl[256];
    const int tid = threadIdx.x;
    {
        const float inv = 1.0f / (float)NB;
        float m = g_stat[ST_S2W + tid] * inv;
        float var = g_stat[ST_Q2W + tid] * inv - m * m;
        float sc = wg2[tid] * rsqrtf(var + 1e-5f);
        scw[tid] = sc; shw[tid] = wbe2[tid] - m * sc;
        m = g_stat[ST_S2L + tid] * inv;
        var = g_stat[ST_Q2L + tid] * inv - m * m;
        sc = lg2[tid] * rsqrtf(var + 1e-5f);
        scl[tid] = sc; shl[tid] = lbe2[tid] - m * sc;
    }
    __syncthreads();
    size_t base = (size_t)blockIdx.x * 1024 + tid * 4;
    int j = (tid * 4) & 255;
    float4 w = *(const float4*)&g_h2w[base];
    float4 l = *(const float4*)&g_h2l[base];
    float4 o;
    o.x = fmaxf(fmaf(w.x, scw[j + 0], shw[j + 0]) + fmaf(l.x, scl[j + 0], shl[j + 0]), 0.0f);
    o.y = fmaxf(fmaf(w.y, scw[j + 1], shw[j + 1]) + fmaf(l.y, scl[j + 1], shl[j + 1]), 0.0f);
    o.z = fmaxf(fmaf(w.z, scw[j + 2], shw[j + 2]) + fmaf(l.z, scl[j + 2], shl[j + 2]), 0.0f);
    o.w = fmaxf(fmaf(w.w, scw[j + 3], shw[j + 3]) + fmaf(l.w, scl[j + 3], shl[j + 3]), 0.0f);
    *(float4*)&out[base] = o;
}

// ---------------- launch ----------------
extern "C" void kernel_launch(void* const* d_in, const int* in_sizes, int n_in,
                              void* d_out, int out_size) {
    const float* x    = (const float*)d_in[0];
    const float* loc  = (const float*)d_in[1];
    const float* wW1  = (const float*)d_in[2];
    const float* wb1  = (const float*)d_in[3];
    const float* wg1  = (const float*)d_in[4];
    const float* wbe1 = (const float*)d_in[5];
    const float* wW2  = (const float*)d_in[6];
    const float* wb2  = (const float*)d_in[7];
    const float* wg2  = (const float*)d_in[8];
    const float* wbe2 = (const float*)d_in[9];
    const float* lW1  = (const float*)d_in[10];
    const float* lb1  = (const float*)d_in[11];
    const float* lg1  = (const float*)d_in[12];
    const float* lbe1 = (const float*)d_in[13];
    const float* lW2  = (const float*)d_in[14];
    const float* lb2  = (const float*)d_in[15];
    const float* lg2  = (const float*)d_in[16];
    const float* lbe2 = (const float*)d_in[17];
    float* out = (float*)d_out;

    float *phi, *statp;
    cudaGetSymbolAddress((void**)&phi, g_phi);
    cudaGetSymbolAddress((void**)&statp, g_stat);

    const int smem_fov = WIN * WSTR * sizeof(float);
    cudaFuncSetAttribute(foveate_kernel, cudaFuncAttributeMaxDynamicSharedMemorySize, smem_fov);

    cudaMemsetAsync(statp, 0, ST_TOTAL * sizeof(float));
    foveate_kernel<<<NB, 256, smem_fov>>>(x, loc, lW1, lb1);
    gemm1_kernel<<<dim3(32, 4), 256>>>(phi, wW1);
    reduce1_kernel<<<128, 256>>>(wb1);
    gemm2_kernel<<<dim3(2, 32, 2), 256>>>(wW2, wb2, lW2, lb2, wg1, wbe1, lW1, lb1, lg1, lbe1);
    final_kernel<<<1024, 256>>>(wg2, wbe2, lg2, lbe2, out);
}

// round 4
// speedup vs baseline: 1.4921x; 1.0761x over previous
#include <cuda_runtime.h>

// ---------------- problem constants ----------------
#define NB 4096
#define IMG 128
#define WIN 112
#define WSTR 113

// stat buffer layout (floats)
#define ST_LOC 0     // 5: Sx, Sy, Qxx, Qyy, Qxy
#define ST_S1  8     // 128
#define ST_Q1  136   // 128
#define ST_S2W 264   // 256
#define ST_Q2W 520   // 256
#define ST_S2L 776   // 256
#define ST_Q2L 1032  // 256
#define ST_TOTAL 1288

// ---------------- scratch ----------------
__device__ float g_phi[NB * 784];
__device__ float g_h1p[4 * NB * 128];   // gemm1 split-K partials
__device__ float g_h1w[NB * 128];
__device__ float g_h1l[NB * 128];
__device__ float g_h2w[NB * 256];
__device__ float g_h2l[NB * 256];
__device__ float g_stat[ST_TOTAL];

// ---------------- packed f32x2 helpers ----------------
__device__ __forceinline__ void ffma2(unsigned long long& d, unsigned long long a, unsigned long long b) {
    asm("fma.rn.f32x2 %0, %1, %2, %0;" : "+l"(d) : "l"(a), "l"(b));
}
__device__ __forceinline__ unsigned long long pk2(float lo, float hi) {
    unsigned long long r; asm("mov.b64 %0, {%1, %2};" : "=l"(r) : "f"(lo), "f"(hi)); return r;
}
__device__ __forceinline__ float2 upk2(unsigned long long v) {
    float2 f; asm("mov.b64 {%0, %1}, %2;" : "=f"(f.x), "=f"(f.y) : "l"(v)); return f;
}

// ---------------- foveate + fused where layer1 + loc moment atomics ----------------
__global__ void foveate_kernel(const float* __restrict__ x, const float* __restrict__ loc,
                               const float* __restrict__ lW1, const float* __restrict__ lb1) {
    extern __shared__ float sh[];  // WIN * WSTR = 12656 floats
    const int b = blockIdx.x;
    const int tid = threadIdx.x;
    const float lx = loc[2 * b + 0];
    const float ly = loc[2 * b + 1];
    const int cx = (int)(0.5f * ((lx + 1.0f) * 128.0f));
    const int cy = (int)(0.5f * ((ly + 1.0f) * 128.0f));
    const int y0 = cy - 56;
    const int x0 = cx - 56;
    const float* img = x + (size_t)b * (IMG * IMG);

    if (tid == 0) {
        atomicAdd(&g_stat[ST_LOC + 0], lx);
        atomicAdd(&g_stat[ST_LOC + 1], ly);
        atomicAdd(&g_stat[ST_LOC + 2], lx * lx);
        atomicAdd(&g_stat[ST_LOC + 3], ly * ly);
        atomicAdd(&g_stat[ST_LOC + 4], lx * ly);
    }

    // vectorized zero (12656 = 4 * 3164)
    {
        float4 z = {0.f, 0.f, 0.f, 0.f};
        float4* sh4 = (float4*)sh;
        for (int i = tid; i < 3164; i += 256) sh4[i] = z;
    }
    __syncthreads();

    // float4 row loads (each image row = 32 aligned float4), scatter into window
    int rlo = max(0, -y0), rhi = min(WIN, IMG - y0);
    int nrows = rhi - rlo;
    for (int t = tid; t < nrows * 32; t += 256) {
        int r = rlo + (t >> 5);
        int c = (t & 31) * 4;
        float4 v = *(const float4*)&img[(y0 + r) * IMG + c];
        int base = r * WSTR - x0;
        int s0 = c - x0;
        float* shr = sh + base;
        if ((unsigned)(s0)     < (unsigned)WIN) shr[c]     = v.x;
        if ((unsigned)(s0 + 1) < (unsigned)WIN) shr[c + 1] = v.y;
        if ((unsigned)(s0 + 2) < (unsigned)WIN) shr[c + 2] = v.z;
        if ((unsigned)(s0 + 3) < (unsigned)WIN) shr[c + 3] = v.w;
    }
    __syncthreads();

    float* out = g_phi + (size_t)b * 784;
    for (int idx = tid; idx < 784; idx += 256) {
        int l = idx / 196;
        int rem = idx - l * 196;
        int i = rem / 14;
        int j = rem - i * 14;
        int k = 1 << l;
        int off = 56 - 7 * k;
        int base = (off + i * k) * WSTR + (off + j * k);
        float s = 0.0f;
        for (int ky = 0; ky < k; ky++) {
            int rb = base + ky * WSTR;
            for (int kx = 0; kx < k; kx++) s += sh[rb + kx];
        }
        out[idx] = s * (1.0f / (float)(k * k));
    }

    if (tid < 128)
        g_h1l[b * 128 + tid] = fmaf(lx, lW1[tid], fmaf(ly, lW1[128 + tid], lb1[tid]));
}

// ---------------- gemm1: split-K partials of phi @ W1 ----------------
// M=4096, N=128, K=784. BM=64, BN=128(=N), BK=8, 256 thr, TM=4, TN=8.
// grid: (64 m-blocks, 4 k-splits) = 256 blocks. Partials -> g_h1p[z].
__global__ void __launch_bounds__(256, 2)
gemm1_kernel(const float* __restrict__ A, const float* __restrict__ W) {
    __shared__ float As[2][8 * 68];
    __shared__ float Bs[2][8 * 128];
    const int tid = threadIdx.x;
    const int m0 = blockIdx.x * 64;
    const int z = blockIdx.y;
    const int kb = z * 200;
    const int ntiles = (z < 3) ? 25 : 23;  // 200/8 or 184/8
    const int K = 784, N = 128;
    const int tx = tid & 15, ty = tid >> 4;

    const int ka = tid & 7, mBase = tid >> 3;   // A: 2 iters, rows mBase + it*32
    const int bc4 = tid & 31, bk = tid >> 5;    // B: one float4, rows 0..7

    float ar[2]; float4 br;
    {
        const float* Ap = A + (size_t)(m0 + mBase) * K + kb + ka;
        ar[0] = Ap[0];
        ar[1] = Ap[(size_t)32 * K];
        br = *(const float4*)&W[(size_t)(kb + bk) * N + bc4 * 4];
        As[0][ka * 68 + mBase] = ar[0];
        As[0][ka * 68 + mBase + 32] = ar[1];
        *(float4*)&Bs[0][bk * 128 + bc4 * 4] = br;
    }
    __syncthreads();

    unsigned long long acc[4][4];
#pragma unroll
    for (int i = 0; i < 4; i++)
#pragma unroll
        for (int j = 0; j < 4; j++) acc[i][j] = 0ull;

    int buf = 0;
    for (int t = 0; t < ntiles; t++) {
        if (t + 1 < ntiles) {
            int k0 = kb + (t + 1) * 8;
            const float* Ap = A + (size_t)(m0 + mBase) * K + k0 + ka;
            ar[0] = Ap[0];
            ar[1] = Ap[(size_t)32 * K];
            br = *(const float4*)&W[(size_t)(k0 + bk) * N + bc4 * 4];
        }
#pragma unroll
        for (int kk = 0; kk < 8; kk++) {
            float4 a0 = *(float4*)&As[buf][kk * 68 + ty * 4];
            float4 b0 = *(float4*)&Bs[buf][kk * 128 + tx * 8];
            float4 b1 = *(float4*)&Bs[buf][kk * 128 + tx * 8 + 4];
            unsigned long long bp0 = pk2(b0.x, b0.y), bp1 = pk2(b0.z, b0.w);
            unsigned long long bp2 = pk2(b1.x, b1.y), bp3 = pk2(b1.z, b1.w);
            float av[4] = {a0.x, a0.y, a0.z, a0.w};
#pragma unroll
            for (int i = 0; i < 4; i++) {
                unsigned long long ad = pk2(av[i], av[i]);
                ffma2(acc[i][0], ad, bp0);
                ffma2(acc[i][1], ad, bp1);
                ffma2(acc[i][2], ad, bp2);
                ffma2(acc[i][3], ad, bp3);
            }
        }
        if (t + 1 < ntiles) {
            buf ^= 1;
            As[buf][ka * 68 + mBase] = ar[0];
            As[buf][ka * 68 + mBase + 32] = ar[1];
            *(float4*)&Bs[buf][bk * 128 + bc4 * 4] = br;
            __syncthreads();
        }
    }

    float* Cp = g_h1p + ((size_t)z * NB + m0) * 128;
#pragma unroll
    for (int i = 0; i < 4; i++) {
        float2 v0 = upk2(acc[i][0]), v1 = upk2(acc[i][1]);
        float2 v2 = upk2(acc[i][2]), v3 = upk2(acc[i][3]);
        float4 o0 = {v0.x, v0.y, v1.x, v1.y};
        float4 o1 = {v2.x, v2.y, v3.x, v3.y};
        float* cp = Cp + (size_t)(ty * 4 + i) * 128 + tx * 8;
        *(float4*)cp = o0;
        *(float4*)(cp + 4) = o1;
    }
}

// ---------------- reduce split-K partials + bias -> h1w, emit BN1 stats ----------------
__global__ void reduce1_kernel(const float* __restrict__ bias) {
    __shared__ float rs[256], rq[256];
    const int tid = threadIdx.x;
    const int col = tid & 127;
    const int grp = tid >> 7;
    const int r0 = blockIdx.x * 32 + grp * 16;
    const float b = bias[col];
    const size_t P = (size_t)NB * 128;
    float s = 0.0f, q = 0.0f;
    for (int r = 0; r < 16; r++) {
        size_t off = (size_t)(r0 + r) * 128 + col;
        float v = g_h1p[off] + g_h1p[P + off] + g_h1p[2 * P + off] + g_h1p[3 * P + off] + b;
        g_h1w[off] = v;
        s += v;
        q = fmaf(v, v, q);
    }
    rs[tid] = s; rq[tid] = q;
    __syncthreads();
    if (tid < 128) {
        atomicAdd(&g_stat[ST_S1 + tid], rs[tid] + rs[tid + 128]);
        atomicAdd(&g_stat[ST_Q1 + tid], rq[tid] + rq[tid + 128]);
    }
}

// ---------------- gemm2: h2 = relu(BN1(h1)) @ W2 + b2, both paths, fused stats ----------------
// M=4096, N=256, K=128. BM=64, BN=128, BK=8, 256 thr, TM=4, TN=8.
// grid: (2 n-blocks, 64 m-blocks, 2 paths) = 256 blocks
__global__ void __launch_bounds__(256, 2)
gemm2_kernel(const float* __restrict__ wW2, const float* __restrict__ wb2,
             const float* __restrict__ lW2, const float* __restrict__ lb2,
             const float* __restrict__ wg1, const float* __restrict__ wbe1,
             const float* __restrict__ lW1, const float* __restrict__ lb1,
             const float* __restrict__ lg1, const float* __restrict__ lbe1) {
    __shared__ float As[2][8 * 68];
    __shared__ float Bs[2][8 * 128];
    __shared__ float sSC[128], sSH[128];

    const int tid = threadIdx.x;
    const int n0 = blockIdx.x * 128;
    const int m0 = blockIdx.y * 64;
    const int path = blockIdx.z;
    const int K = 128, N = 256;
    const int tx = tid & 15, ty = tid >> 4;

    const float* A    = path ? g_h1l : g_h1w;
    const float* W    = path ? lW2 : wW2;
    const float* bias = path ? lb2 : wb2;
    float* C          = path ? g_h2l : g_h2w;
    float* statS = g_stat + (path ? ST_S2L : ST_S2W);
    float* statQ = g_stat + (path ? ST_Q2L : ST_Q2W);

    // prologue: BN1 scale/shift for this path
    if (tid < 128) {
        const float inv = 1.0f / (float)NB;
        float sc, shv;
        if (path == 0) {
            float m = g_stat[ST_S1 + tid] * inv;
            float var = g_stat[ST_Q1 + tid] * inv - m * m;
            sc = wg1[tid] * rsqrtf(var + 1e-5f);
            shv = wbe1[tid] - m * sc;
        } else {
            float m0l = g_stat[0] * inv, m1l = g_stat[1] * inv;
            float v00 = g_stat[2] * inv - m0l * m0l;
            float v11 = g_stat[3] * inv - m1l * m1l;
            float v01 = g_stat[4] * inv - m0l * m1l;
            float W0 = lW1[tid], W1 = lW1[128 + tid];
            float mean = fmaf(m0l, W0, fmaf(m1l, W1, lb1[tid]));
            float var = W0 * W0 * v00 + W1 * W1 * v11 + 2.0f * W0 * W1 * v01;
            sc = lg1[tid] * rsqrtf(var + 1e-5f);
            shv = lbe1[tid] - mean * sc;
        }
        sSC[tid] = sc; sSH[tid] = shv;
    }
    __syncthreads();

    const int ka = tid & 7, mBase = tid >> 3;
    const int bc4 = tid & 31, bk = tid >> 5;

    float ar[2]; float4 br;
    {
        const float* Ap = A + (size_t)(m0 + mBase) * K + ka;
        ar[0] = Ap[0];
        ar[1] = Ap[(size_t)32 * K];
        br = *(const float4*)&W[(size_t)bk * N + n0 + bc4 * 4];
        float scv = sSC[ka], shv = sSH[ka];
        As[0][ka * 68 + mBase]      = fmaxf(fmaf(ar[0], scv, shv), 0.0f);
        As[0][ka * 68 + mBase + 32] = fmaxf(fmaf(ar[1], scv, shv), 0.0f);
        *(float4*)&Bs[0][bk * 128 + bc4 * 4] = br;
    }
    __syncthreads();

    unsigned long long acc[4][4];
#pragma unroll
    for (int i = 0; i < 4; i++)
#pragma unroll
        for (int j = 0; j < 4; j++) acc[i][j] = 0ull;

    int buf = 0;
    const int ntiles = 16;
    for (int t = 0; t < ntiles; t++) {
        if (t + 1 < ntiles) {
            int k0 = (t + 1) * 8;
            const float* Ap = A + (size_t)(m0 + mBase) * K + k0 + ka;
            ar[0] = Ap[0];
            ar[1] = Ap[(size_t)32 * K];
            br = *(const float4*)&W[(size_t)(k0 + bk) * N + n0 + bc4 * 4];
        }
#pragma unroll
        for (int kk = 0; kk < 8; kk++) {
            float4 a0 = *(float4*)&As[buf][kk * 68 + ty * 4];
            float4 b0 = *(float4*)&Bs[buf][kk * 128 + tx * 8];
            float4 b1 = *(float4*)&Bs[buf][kk * 128 + tx * 8 + 4];
            unsigned long long bp0 = pk2(b0.x, b0.y), bp1 = pk2(b0.z, b0.w);
            unsigned long long bp2 = pk2(b1.x, b1.y), bp3 = pk2(b1.z, b1.w);
            float av[4] = {a0.x, a0.y, a0.z, a0.w};
#pragma unroll
            for (int i = 0; i < 4; i++) {
                unsigned long long ad = pk2(av[i], av[i]);
                ffma2(acc[i][0], ad, bp0);
                ffma2(acc[i][1], ad, bp1);
                ffma2(acc[i][2], ad, bp2);
                ffma2(acc[i][3], ad, bp3);
            }
        }
        if (t + 1 < ntiles) {
            buf ^= 1;
            int k0 = (t + 1) * 8;
            float scv = sSC[k0 + ka], shv = sSH[k0 + ka];
            As[buf][ka * 68 + mBase]      = fmaxf(fmaf(ar[0], scv, shv), 0.0f);
            As[buf][ka * 68 + mBase + 32] = fmaxf(fmaf(ar[1], scv, shv), 0.0f);
            *(float4*)&Bs[buf][bk * 128 + bc4 * 4] = br;
            __syncthreads();
        }
    }

    // epilogue: bias, store, column stats
    float bb[8];
#pragma unroll
    for (int j = 0; j < 8; j++) bb[j] = bias[n0 + tx * 8 + j];
    float cv[4][8];
#pragma unroll
    for (int i = 0; i < 4; i++) {
        float2 v0 = upk2(acc[i][0]), v1 = upk2(acc[i][1]);
        float2 v2 = upk2(acc[i][2]), v3 = upk2(acc[i][3]);
        cv[i][0] = v0.x + bb[0]; cv[i][1] = v0.y + bb[1];
        cv[i][2] = v1.x + bb[2]; cv[i][3] = v1.y + bb[3];
        cv[i][4] = v2.x + bb[4]; cv[i][5] = v2.y + bb[5];
        cv[i][6] = v3.x + bb[6]; cv[i][7] = v3.y + bb[7];
        float* cp = C + (size_t)(m0 + ty * 4 + i) * N + n0 + tx * 8;
        float4 o0 = {cv[i][0], cv[i][1], cv[i][2], cv[i][3]};
        float4 o1 = {cv[i][4], cv[i][5], cv[i][6], cv[i][7]};
        *(float4*)cp = o0;
        *(float4*)(cp + 4) = o1;
    }
    float cs[8], cq[8];
#pragma unroll
    for (int j = 0; j < 8; j++) {
        float s = 0, q = 0;
#pragma unroll
        for (int i = 0; i < 4; i++) { s += cv[i][j]; q = fmaf(cv[i][j], cv[i][j], q); }
        cs[j] = s; cq[j] = q;
    }
    __syncthreads();
    float* red = &Bs[0][0];  // 2048 floats
#pragma unroll
    for (int j = 0; j < 8; j++) red[ty * 128 + tx * 8 + j] = cs[j];
    __syncthreads();
    if (tid < 128) {
        float s = 0;
#pragma unroll
        for (int t = 0; t < 16; t++) s += red[t * 128 + tid];
        atomicAdd(&statS[n0 + tid], s);
    }
    __syncthreads();
#pragma unroll
    for (int j = 0; j < 8; j++) red[ty * 128 + tx * 8 + j] = cq[j];
    __syncthreads();
    if (tid < 128) {
        float s = 0;
#pragma unroll
        for (int t = 0; t < 16; t++) s += red[t * 128 + tid];
        atomicAdd(&statQ[n0 + tid], s);
    }
}

// ---------------- final: per-block BN2 + relu(BNw + BNl) ----------------
__global__ void final_kernel(const float* __restrict__ wg2, const float* __restrict__ wbe2,
                             const float* __restrict__ lg2, const float* __restrict__ lbe2,
                             float* __restrict__ out) {
    __shared__ float scw[256], shw[256], scl[256], shl[256];
    const int tid = threadIdx.x;
    {
        const float inv = 1.0f / (float)NB;
        float m = g_stat[ST_S2W + tid] * inv;
        float var = g_stat[ST_Q2W + tid] * inv - m * m;
        float sc = wg2[tid] * rsqrtf(var + 1e-5f);
        scw[tid] = sc; shw[tid] = wbe2[tid] - m * sc;
        m = g_stat[ST_S2L + tid] * inv;
        var = g_stat[ST_Q2L + tid] * inv - m * m;
        sc = lg2[tid] * rsqrtf(var + 1e-5f);
        scl[tid] = sc; shl[tid] = lbe2[tid] - m * sc;
    }
    __syncthreads();
    size_t base = (size_t)blockIdx.x * 1024 + tid * 4;
    int j = (tid * 4) & 255;
    float4 w = *(const float4*)&g_h2w[base];
    float4 l = *(const float4*)&g_h2l[base];
    float4 o;
    o.x = fmaxf(fmaf(w.x, scw[j + 0], shw[j + 0]) + fmaf(l.x, scl[j + 0], shl[j + 0]), 0.0f);
    o.y = fmaxf(fmaf(w.y, scw[j + 1], shw[j + 1]) + fmaf(l.y, scl[j + 1], shl[j + 1]), 0.0f);
    o.z = fmaxf(fmaf(w.z, scw[j + 2], shw[j + 2]) + fmaf(l.z, scl[j + 2], shl[j + 2]), 0.0f);
    o.w = fmaxf(fmaf(w.w, scw[j + 3], shw[j + 3]) + fmaf(l.w, scl[j + 3], shl[j + 3]), 0.0f);
    *(float4*)&out[base] = o;
}

// ---------------- launch ----------------
extern "C" void kernel_launch(void* const* d_in, const int* in_sizes, int n_in,
                              void* d_out, int out_size) {
    const float* x    = (const float*)d_in[0];
    const float* loc  = (const float*)d_in[1];
    const float* wW1  = (const float*)d_in[2];
    const float* wb1  = (const float*)d_in[3];
    const float* wg1  = (const float*)d_in[4];
    const float* wbe1 = (const float*)d_in[5];
    const float* wW2  = (const float*)d_in[6];
    const float* wb2  = (const float*)d_in[7];
    const float* wg2  = (const float*)d_in[8];
    const float* wbe2 = (const float*)d_in[9];
    const float* lW1  = (const float*)d_in[10];
    const float* lb1  = (const float*)d_in[11];
    const float* lg1  = (const float*)d_in[12];
    const float* lbe1 = (const float*)d_in[13];
    const float* lW2  = (const float*)d_in[14];
    const float* lb2  = (const float*)d_in[15];
    const float* lg2  = (const float*)d_in[16];
    const float* lbe2 = (const float*)d_in[17];
    float* out = (float*)d_out;

    float *phi, *statp;
    cudaGetSymbolAddress((void**)&phi, g_phi);
    cudaGetSymbolAddress((void**)&statp, g_stat);

    const int smem_fov = WIN * WSTR * sizeof(float);
    cudaFuncSetAttribute(foveate_kernel, cudaFuncAttributeMaxDynamicSharedMemorySize, smem_fov);

    cudaMemsetAsync(statp, 0, ST_TOTAL * sizeof(float));
    foveate_kernel<<<NB, 256, smem_fov>>>(x, loc, lW1, lb1);
    gemm1_kernel<<<dim3(64, 4), 256>>>(phi, wW1);
    reduce1_kernel<<<128, 256>>>(wb1);
    gemm2_kernel<<<dim3(2, 64, 2), 256>>>(wW2, wb2, lW2, lb2, wg1, wbe1, lW1, lb1, lg1, lbe1);
    final_kernel<<<1024, 256>>>(wg2, wbe2, lg2, lbe2, out);
}